// round 1
// baseline (speedup 1.0000x reference)
#include <cuda_runtime.h>
#include <cuda_bf16.h>
#include <cstdint>

// Problem constants (fixed by the dataset)
#define B_IMG 4096
#define V_TXT 5
#define D_DIM 512
#define N_TXT (B_IMG * V_TXT)        // 20480
#define SCALE_F 14.285714285714286f  // 1/0.07
#define MSHIFT_F 14.285714285714286f // fixed LSE shift (max possible |logit|)

// ---------------- device scratch (static: no runtime allocation) ----------------
__device__ __nv_bfloat16 g_imgb[(size_t)B_IMG * D_DIM];  // 4 MB
__device__ __nv_bfloat16 g_txtb[(size_t)N_TXT * D_DIM];  // 20 MB
__device__ float g_rowsum[B_IMG];
__device__ float g_colsum[N_TXT];
__device__ float g_possum;

// ---------------- init: zero accumulators every launch (graph-replay safe) ------
__global__ void init_kernel() {
    int idx = blockIdx.x * blockDim.x + threadIdx.x;
    if (idx < B_IMG) g_rowsum[idx] = 0.0f;
    if (idx < N_TXT) g_colsum[idx] = 0.0f;
    if (idx == 0)    g_possum = 0.0f;
}

// ---------------- fp32 -> bf16 convert (halves GEMM-side memory traffic) --------
__global__ void convert_kernel(const float* __restrict__ img,
                               const float* __restrict__ txt) {
    const int IMG4 = B_IMG * D_DIM / 4;       // 524288
    const int TOT4 = IMG4 + N_TXT * D_DIM / 4;
    for (int i = blockIdx.x * blockDim.x + threadIdx.x; i < TOT4;
         i += gridDim.x * blockDim.x) {
        float4 v;
        __nv_bfloat16* dst;
        if (i < IMG4) {
            v = reinterpret_cast<const float4*>(img)[i];
            dst = g_imgb + 4 * (size_t)i;
        } else {
            int j = i - IMG4;
            v = reinterpret_cast<const float4*>(txt)[j];
            dst = g_txtb + 4 * (size_t)j;
        }
        __nv_bfloat162 p0 = __floats2bfloat162_rn(v.x, v.y);
        __nv_bfloat162 p1 = __floats2bfloat162_rn(v.z, v.w);
        reinterpret_cast<__nv_bfloat162*>(dst)[0] = p0;
        reinterpret_cast<__nv_bfloat162*>(dst)[1] = p1;
    }
}

// ---------------- fused GEMM + exp + row/col reduction ---------------------------
// Tile: 128(M) x 128(N), BK=16, 8 warps as 2x4 (warp tile 64x32),
// mma.sync.m16n8k16 bf16 -> f32. cp.async double-buffered smem (padded stride
// 24 halves => conflict-free 32-bit fragment loads).

__device__ __forceinline__ void cp_async16(void* smem_dst, const void* gsrc) {
    uint32_t s = (uint32_t)__cvta_generic_to_shared(smem_dst);
    asm volatile("cp.async.ca.shared.global [%0], [%1], 16;\n" ::"r"(s), "l"(gsrc));
}

__device__ __forceinline__ void mma16816(float* c, const uint32_t* a, const uint32_t* b) {
    asm volatile(
        "mma.sync.aligned.m16n8k16.row.col.f32.bf16.bf16.f32 "
        "{%0,%1,%2,%3}, {%4,%5,%6,%7}, {%8,%9}, {%0,%1,%2,%3};\n"
        : "+f"(c[0]), "+f"(c[1]), "+f"(c[2]), "+f"(c[3])
        : "r"(a[0]), "r"(a[1]), "r"(a[2]), "r"(a[3]), "r"(b[0]), "r"(b[1]));
}

#define LDH 24        // smem row stride in halves (pad 16 -> 24: conflict-free)
#define STAGE_H (128 * LDH)  // halves per stage per tensor

__global__ void __launch_bounds__(256, 2) gemm_fused_kernel() {
    __shared__ __nv_bfloat16 As[2 * STAGE_H];
    __shared__ __nv_bfloat16 Bs[2 * STAGE_H];

    const int tid   = threadIdx.x;
    const int lane  = tid & 31;
    const int warp  = tid >> 5;
    const int g     = lane >> 2;   // group id (row within fragment)
    const int t     = lane & 3;    // thread-in-group (k/col pairs)
    const int warpM = warp >> 2;   // 0..1
    const int warpN = warp & 3;    // 0..3
    const int rowBase = blockIdx.y * 128;
    const int colBase = blockIdx.x * 128;

    // loader mapping: each thread copies one 16B chunk of A and one of B per stage
    const int ldRow  = tid >> 1;          // 0..127
    const int ldHalf = (tid & 1) * 8;     // 0 or 8 (halves)
    const __nv_bfloat16* gA = g_imgb + (size_t)(rowBase + ldRow) * D_DIM + ldHalf;
    const __nv_bfloat16* gB = g_txtb + (size_t)(colBase + ldRow) * D_DIM + ldHalf;
    __nv_bfloat16* sA = &As[ldRow * LDH + ldHalf];
    __nv_bfloat16* sB = &Bs[ldRow * LDH + ldHalf];

    float acc[4][4][4];
#pragma unroll
    for (int mi = 0; mi < 4; mi++)
#pragma unroll
        for (int ni = 0; ni < 4; ni++)
#pragma unroll
            for (int r = 0; r < 4; r++) acc[mi][ni][r] = 0.0f;

    // prefetch stage 0
    cp_async16(sA, gA);
    cp_async16(sB, gB);
    asm volatile("cp.async.commit_group;\n" ::: "memory");

    const int NSTEP = D_DIM / 16;  // 32
#pragma unroll 1
    for (int kc = 0; kc < NSTEP; kc++) {
        if (kc + 1 < NSTEP) {
            int st = (kc + 1) & 1;
            int k0 = (kc + 1) * 16;
            cp_async16(sA + st * STAGE_H, gA + k0);
            cp_async16(sB + st * STAGE_H, gB + k0);
            asm volatile("cp.async.commit_group;\n" ::: "memory");
            asm volatile("cp.async.wait_group 1;\n" ::: "memory");
        } else {
            asm volatile("cp.async.wait_group 0;\n" ::: "memory");
        }
        __syncthreads();

        const int buf = kc & 1;
        const uint32_t* A32 = reinterpret_cast<const uint32_t*>(As + buf * STAGE_H);
        const uint32_t* B32 = reinterpret_cast<const uint32_t*>(Bs + buf * STAGE_H);

        uint32_t a[4][4], b[4][2];
#pragma unroll
        for (int mi = 0; mi < 4; mi++) {
            int r0 = warpM * 64 + mi * 16 + g;
            a[mi][0] = A32[r0 * (LDH / 2) + t];
            a[mi][1] = A32[(r0 + 8) * (LDH / 2) + t];
            a[mi][2] = A32[r0 * (LDH / 2) + t + 4];
            a[mi][3] = A32[(r0 + 8) * (LDH / 2) + t + 4];
        }
#pragma unroll
        for (int ni = 0; ni < 4; ni++) {
            int c0 = warpN * 32 + ni * 8 + g;
            b[ni][0] = B32[c0 * (LDH / 2) + t];
            b[ni][1] = B32[c0 * (LDH / 2) + t + 4];
        }
#pragma unroll
        for (int mi = 0; mi < 4; mi++)
#pragma unroll
            for (int ni = 0; ni < 4; ni++) mma16816(acc[mi][ni], a[mi], b[ni]);

        __syncthreads();
    }

    // ---------------- epilogue: exp + row/col partial sums, register-only -------
    float rp[4][2];  // [mi][row g / g+8]: partial row sums over this warp's 32 cols
    float cp[4][2];  // [ni][col 2t / 2t+1]: partial col sums over this warp's 64 rows
#pragma unroll
    for (int i = 0; i < 4; i++) { rp[i][0] = rp[i][1] = cp[i][0] = cp[i][1] = 0.0f; }
    float pos = 0.0f;

#pragma unroll
    for (int mi = 0; mi < 4; mi++) {
        const int r0 = rowBase + warpM * 64 + mi * 16 + g;
        const int r1 = r0 + 8;
#pragma unroll
        for (int ni = 0; ni < 4; ni++) {
            const int c0 = colBase + warpN * 32 + ni * 8 + 2 * t;
            const int c1 = c0 + 1;
            float l00 = acc[mi][ni][0] * SCALE_F;
            float l01 = acc[mi][ni][1] * SCALE_F;
            float l10 = acc[mi][ni][2] * SCALE_F;
            float l11 = acc[mi][ni][3] * SCALE_F;
            float e00 = __expf(l00 - MSHIFT_F);
            float e01 = __expf(l01 - MSHIFT_F);
            float e10 = __expf(l10 - MSHIFT_F);
            float e11 = __expf(l11 - MSHIFT_F);
            rp[mi][0] += e00 + e01;
            rp[mi][1] += e10 + e11;
            cp[ni][0] += e00 + e10;
            cp[ni][1] += e01 + e11;
            // positive entries: col j in [i*V, i*V+V)
            int p0 = r0 * V_TXT;
            int p1 = r1 * V_TXT;
            if (c0 >= p0 && c0 < p0 + V_TXT) pos += l00;
            if (c1 >= p0 && c1 < p0 + V_TXT) pos += l01;
            if (c0 >= p1 && c0 < p1 + V_TXT) pos += l10;
            if (c1 >= p1 && c1 < p1 + V_TXT) pos += l11;
        }
    }

    // row sums: reduce across the 4 lanes sharing a row (t bits)
#pragma unroll
    for (int mi = 0; mi < 4; mi++) {
#pragma unroll
        for (int rr = 0; rr < 2; rr++) {
            float v = rp[mi][rr];
            v += __shfl_xor_sync(0xffffffffu, v, 1);
            v += __shfl_xor_sync(0xffffffffu, v, 2);
            if (t == 0) {
                int row = rowBase + warpM * 64 + mi * 16 + g + rr * 8;
                atomicAdd(&g_rowsum[row], v);
            }
        }
    }
    // col sums: reduce across the 8 lanes sharing a column (g bits)
#pragma unroll
    for (int ni = 0; ni < 4; ni++) {
#pragma unroll
        for (int cc = 0; cc < 2; cc++) {
            float v = cp[ni][cc];
            v += __shfl_xor_sync(0xffffffffu, v, 4);
            v += __shfl_xor_sync(0xffffffffu, v, 8);
            v += __shfl_xor_sync(0xffffffffu, v, 16);
            if (g == 0) {
                int col = colBase + warpN * 32 + ni * 8 + 2 * t + cc;
                atomicAdd(&g_colsum[col], v);
            }
        }
    }
    if (pos != 0.0f) atomicAdd(&g_possum, pos);
}

// ---------------- finalize: fp64 log-sum + scalar loss ---------------------------
__global__ void final_kernel(float* out, int out_size) {
    __shared__ double sh[256];
    int tid = threadIdx.x;
    double s = 0.0;
    for (int i = tid; i < B_IMG; i += 256)
        s += log((double)g_rowsum[i]) * (1.0 / B_IMG);
    for (int j = tid; j < N_TXT; j += 256)
        s += log((double)g_colsum[j]) * (1.0 / N_TXT);
    sh[tid] = s;
    __syncthreads();
    for (int off = 128; off > 0; off >>= 1) {
        if (tid < off) sh[tid] += sh[tid + off];
        __syncthreads();
    }
    if (tid == 0) {
        double loss = 0.5 * (sh[0] + 2.0 * (double)MSHIFT_F)
                      - (double)g_possum / (double)N_TXT;
        for (int k = 0; k < out_size; k++) out[k] = (float)loss;
    }
}

// ---------------- launch ---------------------------------------------------------
extern "C" void kernel_launch(void* const* d_in, const int* in_sizes, int n_in,
                              void* d_out, int out_size) {
    const float* img = (const float*)d_in[0];  // (4096, 512) fp32
    const float* txt = (const float*)d_in[1];  // (4096, 5, 512) fp32
    (void)in_sizes; (void)n_in;

    init_kernel<<<(N_TXT + 255) / 256, 256>>>();
    convert_kernel<<<2048, 256>>>(img, txt);
    dim3 grid(N_TXT / 128, B_IMG / 128);  // (160, 32) tiles
    gemm_fused_kernel<<<grid, 256>>>();
    final_kernel<<<1, 256>>>((float*)d_out, out_size);
}

// round 4
// speedup vs baseline: 4.6798x; 4.6798x over previous
#include <cuda_runtime.h>
#include <cuda_bf16.h>
#include <cstdint>

// Problem constants
#define B_IMG 4096
#define V_TXT 5
#define D_DIM 512
#define N_TXT (B_IMG * V_TXT)         // 20480
#define SCALE_F 14.285714285714286f   // 1/0.07
#define MSHIFT_F 14.285714285714286f

// Arch-specific feature detection (tcgen05 requires an sm_103a/f device pass)
#if defined(__CUDA_ARCH_FEAT_SM103_ALL) || defined(__CUDA_ARCH_SPECIFIC__) || defined(__CUDA_ARCH_FAMILY_SPECIFIC__)
#define HAS_TCGEN05 1
#else
#define HAS_TCGEN05 0
#endif

// ---------------- device scratch ----------------
__device__ __nv_bfloat16 g_imgb[(size_t)B_IMG * D_DIM];
__device__ __nv_bfloat16 g_txtb[(size_t)N_TXT * D_DIM];
__device__ float g_rowsum[B_IMG];
__device__ float g_colsum[N_TXT];
__device__ float g_possum;   // RAW (unscaled) positive-logit sum
__device__ float g_logsum;

// ---------------- init ----------------
__global__ void init_kernel() {
    int idx = blockIdx.x * blockDim.x + threadIdx.x;
    if (idx < B_IMG) g_rowsum[idx] = 0.0f;
    if (idx < N_TXT) g_colsum[idx] = 0.0f;
    if (idx == 0) { g_possum = 0.0f; g_logsum = 0.0f; }
}

// ---------------- fp32 -> bf16 convert ----------------
__global__ void convert_kernel(const float* __restrict__ img,
                               const float* __restrict__ txt) {
    const int IMG4 = B_IMG * D_DIM / 4;
    const int TOT4 = IMG4 + N_TXT * D_DIM / 4;
    for (int i = blockIdx.x * blockDim.x + threadIdx.x; i < TOT4;
         i += gridDim.x * blockDim.x) {
        float4 v; __nv_bfloat16* dst;
        if (i < IMG4) { v = reinterpret_cast<const float4*>(img)[i]; dst = g_imgb + 4 * (size_t)i; }
        else { int j = i - IMG4; v = reinterpret_cast<const float4*>(txt)[j]; dst = g_txtb + 4 * (size_t)j; }
        reinterpret_cast<__nv_bfloat162*>(dst)[0] = __floats2bfloat162_rn(v.x, v.y);
        reinterpret_cast<__nv_bfloat162*>(dst)[1] = __floats2bfloat162_rn(v.z, v.w);
    }
}

// ================= PATH A: tcgen05 (only in sm_103a/f passes) =================
#define TC_TILE_M 128
#define TC_TILE_N 512
#define TC_BK 64
#define TC_NCHUNK (D_DIM / TC_BK)     // 8

#define SM_TMEMPTR 0u
#define SM_MBAR0   8u
#define SM_MBAR1   16u
#define SM_A0      1024u
#define SM_A1      17408u
#define SM_B0      33792u
#define SM_B1      99328u
#define SM_TOTAL   164864u

#define MMA_IDESC ((1u<<4)|(1u<<7)|(1u<<10)|((256u/8u)<<17)|((128u/16u)<<24))
#define SWZ(x) ((x) ^ (((x) >> 3) & 0x70))

__device__ __forceinline__ uint32_t smem_u32(const void* p) {
    return (uint32_t)__cvta_generic_to_shared(p);
}
__device__ __forceinline__ void cp16(uint32_t saddr, const void* g) {
    asm volatile("cp.async.cg.shared.global [%0], [%1], 16;\n" ::"r"(saddr), "l"(g));
}
__device__ __forceinline__ void mbar_init(uint32_t a, uint32_t cnt) {
    asm volatile("mbarrier.init.shared.b64 [%0], %1;" ::"r"(a), "r"(cnt) : "memory");
}
__device__ __forceinline__ void mbar_wait(uint32_t a, uint32_t parity) {
    uint32_t done;
    asm volatile(
        "{\n\t.reg .pred p;\n\t"
        "mbarrier.try_wait.parity.acquire.cta.shared::cta.b64 p, [%1], %2;\n\t"
        "selp.b32 %0, 1, 0, p;\n\t}"
        : "=r"(done) : "r"(a), "r"(parity) : "memory");
    if (!done) {
        asm volatile(
            "{\n\t.reg .pred P1;\n\t"
            "W_%=:\n\t"
            "mbarrier.try_wait.parity.acquire.cta.shared::cta.b64 P1, [%0], %1, 0x989680;\n\t"
            "@P1 bra.uni D_%=;\n\t"
            "bra.uni W_%=;\n\t"
            "D_%=:\n\t}"
            :: "r"(a), "r"(parity) : "memory");
    }
}

#if HAS_TCGEN05
__device__ __forceinline__ uint64_t make_desc_sw128(uint32_t addr) {
    const uint64_t base = (uint64_t(2) << 61) | (uint64_t(1) << 46) |
                          (uint64_t(64) << 32) | (uint64_t(1) << 16);
    return base | ((uint64_t)(addr >> 4) & 0x3FFF);
}
__device__ __forceinline__ void mma_f16_ss(uint32_t d, uint64_t ad, uint64_t bd,
                                           uint32_t idesc, uint32_t en) {
    asm volatile(
        "{\n\t.reg .pred p;\n\t"
        "setp.ne.u32 p, %4, 0;\n\t"
        "tcgen05.mma.cta_group::1.kind::f16 [%0], %1, %2, %3, {%5,%5,%5,%5}, p;\n\t}"
        :: "r"(d), "l"(ad), "l"(bd), "r"(idesc), "r"(en), "r"(0u) : "memory");
}
__device__ __forceinline__ void tc_load_chunk(uint32_t smem_base, int buf, int kc,
                                              int rowBase, int colBase, int tid) {
    uint32_t aoff = buf ? SM_A1 : SM_A0;
    uint32_t boff = buf ? SM_B1 : SM_B0;
    const __nv_bfloat16* srcA = g_imgb + (size_t)rowBase * D_DIM + kc * TC_BK;
    const __nv_bfloat16* srcB = g_txtb + (size_t)colBase * D_DIM + kc * TC_BK;
#pragma unroll
    for (int i = 0; i < 4; i++) {
        int idx = tid + i * 256;
        int row = idx >> 3, seg = idx & 7;
        cp16(smem_base + aoff + SWZ((uint32_t)(row * 128 + seg * 16)),
             srcA + (size_t)row * D_DIM + seg * 8);
    }
#pragma unroll
    for (int i = 0; i < 16; i++) {
        int idx = tid + i * 256;
        int row = idx >> 3, seg = idx & 7;
        cp16(smem_base + boff + SWZ((uint32_t)(row * 128 + seg * 16)),
             srcB + (size_t)row * D_DIM + seg * 8);
    }
    asm volatile("cp.async.commit_group;\n" ::: "memory");
}
#endif  // HAS_TCGEN05

__global__ void __launch_bounds__(256, 1) gemm_tc_kernel() {
#if HAS_TCGEN05
    extern __shared__ char smem[];
    uint32_t smem_base = smem_u32(smem);
    const int tid = threadIdx.x;
    const int w = tid >> 5, lane = tid & 31;
    const int rowBase = blockIdx.y * TC_TILE_M;
    const int colBase = blockIdx.x * TC_TILE_N;

    if (w == 0) {
        asm volatile("tcgen05.alloc.cta_group::1.sync.aligned.shared::cta.b32 [%0], %1;"
                     ::"r"(smem_base + SM_TMEMPTR), "r"(512u) : "memory");
        asm volatile("tcgen05.relinquish_alloc_permit.cta_group::1.sync.aligned;");
    }
    if (tid == 0) { mbar_init(smem_base + SM_MBAR0, 1); mbar_init(smem_base + SM_MBAR1, 1); }
    __syncthreads();
    uint32_t tmem_base;
    asm volatile("ld.shared.b32 %0, [%1];" : "=r"(tmem_base) : "r"(smem_base + SM_TMEMPTR));

    tc_load_chunk(smem_base, 0, 0, rowBase, colBase, tid);

#pragma unroll 1
    for (int c = 0; c < TC_NCHUNK; c++) {
        if (c + 1 < TC_NCHUNK) {
            if (c >= 1) {
                uint32_t mb = ((c - 1) & 1) ? (smem_base + SM_MBAR1) : (smem_base + SM_MBAR0);
                mbar_wait(mb, ((c - 1) >> 1) & 1);
            }
            tc_load_chunk(smem_base, (c + 1) & 1, c + 1, rowBase, colBase, tid);
            asm volatile("cp.async.wait_group 1;\n" ::: "memory");
        } else {
            asm volatile("cp.async.wait_group 0;\n" ::: "memory");
        }
        __syncthreads();

        if (tid == 0) {
            asm volatile("fence.proxy.async.shared::cta;" ::: "memory");
            uint32_t abase = smem_base + ((c & 1) ? SM_A1 : SM_A0);
            uint32_t bbase = smem_base + ((c & 1) ? SM_B1 : SM_B0);
            uint64_t ad = make_desc_sw128(abase);
            uint64_t bd = make_desc_sw128(bbase);
#pragma unroll
            for (int nh = 0; nh < 2; nh++)
#pragma unroll
                for (int k = 0; k < 4; k++)
                    mma_f16_ss(tmem_base + nh * 256, ad + k * 2,
                               bd + nh * 2048 + k * 2, MMA_IDESC,
                               (uint32_t)((c > 0) || (k > 0)));
            uint32_t mb = (c & 1) ? (smem_base + SM_MBAR1) : (smem_base + SM_MBAR0);
            asm volatile(
                "tcgen05.commit.cta_group::1.mbarrier::arrive::one.shared::cluster.b64 [%0];"
                ::"r"(mb) : "memory");
        }
    }

    mbar_wait(smem_base + SM_MBAR1, 1);
    asm volatile("tcgen05.fence::after_thread_sync;" ::: "memory");

    const int half = w >> 2, sp = w & 3;
    const int row = rowBase + sp * 32 + lane;
    float rowacc = 0.0f, pos = 0.0f;
    const int pstart = row * V_TXT - colBase - half * 256;

#pragma unroll 1
    for (int ch = 0; ch < 8; ch++) {
        uint32_t r[32];
        uint32_t taddr = tmem_base + half * 256 + ch * 32;
        asm volatile(
            "tcgen05.ld.sync.aligned.32x32b.x32.b32 "
            "{%0,%1,%2,%3,%4,%5,%6,%7,%8,%9,%10,%11,%12,%13,%14,%15,"
            "%16,%17,%18,%19,%20,%21,%22,%23,%24,%25,%26,%27,%28,%29,%30,%31}, [%32];"
            : "=r"(r[0]), "=r"(r[1]), "=r"(r[2]), "=r"(r[3]), "=r"(r[4]), "=r"(r[5]),
              "=r"(r[6]), "=r"(r[7]), "=r"(r[8]), "=r"(r[9]), "=r"(r[10]), "=r"(r[11]),
              "=r"(r[12]), "=r"(r[13]), "=r"(r[14]), "=r"(r[15]), "=r"(r[16]), "=r"(r[17]),
              "=r"(r[18]), "=r"(r[19]), "=r"(r[20]), "=r"(r[21]), "=r"(r[22]), "=r"(r[23]),
              "=r"(r[24]), "=r"(r[25]), "=r"(r[26]), "=r"(r[27]), "=r"(r[28]), "=r"(r[29]),
              "=r"(r[30]), "=r"(r[31])
            : "r"(taddr));
        asm volatile("tcgen05.wait::ld.sync.aligned;" ::: "memory");

        float v[32];
#pragma unroll
        for (int cc = 0; cc < 32; cc++) {
            float a = __uint_as_float(r[cc]);
            int lc = ch * 32 + cc;
            if (lc >= pstart && lc < pstart + V_TXT) pos += a;
            float e = __expf(fmaf(a, SCALE_F, -MSHIFT_F));
            v[cc] = e;
            rowacc += e;
        }
#pragma unroll
        for (int off = 16; off >= 1; off >>= 1) {
#pragma unroll
            for (int cc = 0; cc < 16; cc++) {
                if (cc < off) {
                    float sent = (lane & off) ? v[cc] : v[cc + off];
                    float rcv = __shfl_xor_sync(0xffffffffu, sent, off);
                    float keep = (lane & off) ? v[cc + off] : v[cc];
                    v[cc] = keep + rcv;
                }
            }
        }
        atomicAdd(&g_colsum[colBase + half * 256 + ch * 32 + lane], v[0]);
    }
    atomicAdd(&g_rowsum[row], rowacc);
    if (pos != 0.0f) atomicAdd(&g_possum, pos);

    __syncthreads();
    if (w == 0) {
        asm volatile("tcgen05.dealloc.cta_group::1.sync.aligned.b32 %0, %1;"
                     ::"r"(tmem_base), "r"(512u));
    }
#endif  // HAS_TCGEN05
}

// ================= PATH B: HMMA mma.sync fallback (plain sm_103) =============
__device__ __forceinline__ void mma16816(float* c, const uint32_t* a, const uint32_t* b) {
    asm volatile(
        "mma.sync.aligned.m16n8k16.row.col.f32.bf16.bf16.f32 "
        "{%0,%1,%2,%3}, {%4,%5,%6,%7}, {%8,%9}, {%0,%1,%2,%3};\n"
        : "+f"(c[0]), "+f"(c[1]), "+f"(c[2]), "+f"(c[3])
        : "r"(a[0]), "r"(a[1]), "r"(a[2]), "r"(a[3]), "r"(b[0]), "r"(b[1]));
}
__device__ __forceinline__ void cpa16(void* smem_dst, const void* gsrc) {
    uint32_t s = (uint32_t)__cvta_generic_to_shared(smem_dst);
    asm volatile("cp.async.ca.shared.global [%0], [%1], 16;\n" ::"r"(s), "l"(gsrc));
}
#define LDH 24
#define STAGE_H (128 * LDH)

__global__ void __launch_bounds__(256, 2) gemm_hmma_kernel() {
#if !HAS_TCGEN05
    __shared__ __nv_bfloat16 As[2 * STAGE_H];
    __shared__ __nv_bfloat16 Bs[2 * STAGE_H];

    const int tid = threadIdx.x;
    const int lane = tid & 31;
    const int warp = tid >> 5;
    const int g = lane >> 2;
    const int t = lane & 3;
    const int warpM = warp >> 2;
    const int warpN = warp & 3;
    const int rowBase = blockIdx.y * 128;
    const int colBase = blockIdx.x * 128;

    const int ldRow = tid >> 1;
    const int ldHalf = (tid & 1) * 8;
    const __nv_bfloat16* gA = g_imgb + (size_t)(rowBase + ldRow) * D_DIM + ldHalf;
    const __nv_bfloat16* gB = g_txtb + (size_t)(colBase + ldRow) * D_DIM + ldHalf;
    __nv_bfloat16* sA = &As[ldRow * LDH + ldHalf];
    __nv_bfloat16* sB = &Bs[ldRow * LDH + ldHalf];

    float acc[4][4][4];
#pragma unroll
    for (int mi = 0; mi < 4; mi++)
#pragma unroll
        for (int ni = 0; ni < 4; ni++)
#pragma unroll
            for (int r = 0; r < 4; r++) acc[mi][ni][r] = 0.0f;

    cpa16(sA, gA);
    cpa16(sB, gB);
    asm volatile("cp.async.commit_group;\n" ::: "memory");

    const int NSTEP = D_DIM / 16;
#pragma unroll 1
    for (int kc = 0; kc < NSTEP; kc++) {
        if (kc + 1 < NSTEP) {
            int st = (kc + 1) & 1;
            int k0 = (kc + 1) * 16;
            cpa16(sA + st * STAGE_H, gA + k0);
            cpa16(sB + st * STAGE_H, gB + k0);
            asm volatile("cp.async.commit_group;\n" ::: "memory");
            asm volatile("cp.async.wait_group 1;\n" ::: "memory");
        } else {
            asm volatile("cp.async.wait_group 0;\n" ::: "memory");
        }
        __syncthreads();

        const int buf = kc & 1;
        const uint32_t* A32 = reinterpret_cast<const uint32_t*>(As + buf * STAGE_H);
        const uint32_t* B32 = reinterpret_cast<const uint32_t*>(Bs + buf * STAGE_H);

        uint32_t a[4][4], b[4][2];
#pragma unroll
        for (int mi = 0; mi < 4; mi++) {
            int r0 = warpM * 64 + mi * 16 + g;
            a[mi][0] = A32[r0 * (LDH / 2) + t];
            a[mi][1] = A32[(r0 + 8) * (LDH / 2) + t];
            a[mi][2] = A32[r0 * (LDH / 2) + t + 4];
            a[mi][3] = A32[(r0 + 8) * (LDH / 2) + t + 4];
        }
#pragma unroll
        for (int ni = 0; ni < 4; ni++) {
            int c0 = warpN * 32 + ni * 8 + g;
            b[ni][0] = B32[c0 * (LDH / 2) + t];
            b[ni][1] = B32[c0 * (LDH / 2) + t + 4];
        }
#pragma unroll
        for (int mi = 0; mi < 4; mi++)
#pragma unroll
            for (int ni = 0; ni < 4; ni++) mma16816(acc[mi][ni], a[mi], b[ni]);

        __syncthreads();
    }

    float rp[4][2], cp[4][2];
#pragma unroll
    for (int i = 0; i < 4; i++) { rp[i][0] = rp[i][1] = cp[i][0] = cp[i][1] = 0.0f; }
    float pos = 0.0f;

#pragma unroll
    for (int mi = 0; mi < 4; mi++) {
        const int r0 = rowBase + warpM * 64 + mi * 16 + g;
        const int r1 = r0 + 8;
#pragma unroll
        for (int ni = 0; ni < 4; ni++) {
            const int c0 = colBase + warpN * 32 + ni * 8 + 2 * t;
            const int c1 = c0 + 1;
            float e00 = __expf(fmaf(acc[mi][ni][0], SCALE_F, -MSHIFT_F));
            float e01 = __expf(fmaf(acc[mi][ni][1], SCALE_F, -MSHIFT_F));
            float e10 = __expf(fmaf(acc[mi][ni][2], SCALE_F, -MSHIFT_F));
            float e11 = __expf(fmaf(acc[mi][ni][3], SCALE_F, -MSHIFT_F));
            rp[mi][0] += e00 + e01;
            rp[mi][1] += e10 + e11;
            cp[ni][0] += e00 + e10;
            cp[ni][1] += e01 + e11;
            int p0 = r0 * V_TXT;
            int p1 = r1 * V_TXT;
            if (c0 >= p0 && c0 < p0 + V_TXT) pos += acc[mi][ni][0];  // RAW
            if (c1 >= p0 && c1 < p0 + V_TXT) pos += acc[mi][ni][1];
            if (c0 >= p1 && c0 < p1 + V_TXT) pos += acc[mi][ni][2];
            if (c1 >= p1 && c1 < p1 + V_TXT) pos += acc[mi][ni][3];
        }
    }

#pragma unroll
    for (int mi = 0; mi < 4; mi++)
#pragma unroll
        for (int rr = 0; rr < 2; rr++) {
            float v = rp[mi][rr];
            v += __shfl_xor_sync(0xffffffffu, v, 1);
            v += __shfl_xor_sync(0xffffffffu, v, 2);
            if (t == 0)
                atomicAdd(&g_rowsum[rowBase + warpM * 64 + mi * 16 + g + rr * 8], v);
        }
#pragma unroll
    for (int ni = 0; ni < 4; ni++)
#pragma unroll
        for (int cc = 0; cc < 2; cc++) {
            float v = cp[ni][cc];
            v += __shfl_xor_sync(0xffffffffu, v, 4);
            v += __shfl_xor_sync(0xffffffffu, v, 8);
            v += __shfl_xor_sync(0xffffffffu, v, 16);
            if (g == 0)
                atomicAdd(&g_colsum[colBase + warpN * 32 + ni * 8 + 2 * t + cc], v);
        }
    if (pos != 0.0f) atomicAdd(&g_possum, pos);
#endif  // !HAS_TCGEN05
}

// ---------------- parallel log reduction + writer ----------------
__global__ void reduce_kernel() {
    float s = 0.0f;
    for (int i = blockIdx.x * blockDim.x + threadIdx.x; i < B_IMG;
         i += gridDim.x * blockDim.x)
        s += logf(g_rowsum[i]) * (1.0f / B_IMG);
    for (int j = blockIdx.x * blockDim.x + threadIdx.x; j < N_TXT;
         j += gridDim.x * blockDim.x)
        s += logf(g_colsum[j]) * (1.0f / N_TXT);
#pragma unroll
    for (int off = 16; off >= 1; off >>= 1) s += __shfl_xor_sync(0xffffffffu, s, off);
    __shared__ float sh[8];
    int w = threadIdx.x >> 5, lane = threadIdx.x & 31;
    if (lane == 0) sh[w] = s;
    __syncthreads();
    if (threadIdx.x == 0) {
        float b = 0.0f;
        for (int k = 0; k < 8; k++) b += sh[k];
        atomicAdd(&g_logsum, b);
    }
}

__global__ void write_kernel(float* out, int out_size) {
    float loss = 0.5f * (g_logsum + 2.0f * MSHIFT_F)
                 - SCALE_F * g_possum / (float)N_TXT;
    for (int k = 0; k < out_size; k++) out[k] = loss;
}

// ---------------- launch ----------------
extern "C" void kernel_launch(void* const* d_in, const int* in_sizes, int n_in,
                              void* d_out, int out_size) {
    const float* img = (const float*)d_in[0];
    const float* txt = (const float*)d_in[1];
    (void)in_sizes; (void)n_in;

    static int smem_set = 0;
    if (!smem_set) {
        cudaFuncSetAttribute(gemm_tc_kernel,
                             cudaFuncAttributeMaxDynamicSharedMemorySize, SM_TOTAL);
        smem_set = 1;
    }

    init_kernel<<<(N_TXT + 255) / 256, 256>>>();
    convert_kernel<<<2048, 256>>>(img, txt);

    // Exactly one of these has a compiled body; the other is an empty kernel.
    dim3 grid_tc(N_TXT / TC_TILE_N, B_IMG / TC_TILE_M);   // (40, 32)
    gemm_tc_kernel<<<grid_tc, 256, SM_TOTAL>>>();
    dim3 grid_hm(N_TXT / 128, B_IMG / 128);               // (160, 32)
    gemm_hmma_kernel<<<grid_hm, 256>>>();

    reduce_kernel<<<64, 256>>>();
    write_kernel<<<1, 1>>>((float*)d_out, out_size);
}

// round 5
// speedup vs baseline: 4.8233x; 1.0307x over previous
#include <cuda_runtime.h>
#include <cuda_bf16.h>
#include <cstdint>

// Problem constants
#define B_IMG 4096
#define V_TXT 5
#define D_DIM 512
#define N_TXT (B_IMG * V_TXT)         // 20480
#define SCALE_F 14.285714285714286f   // 1/0.07
#define MSHIFT_F 14.285714285714286f

// Arch-specific feature detection (tcgen05 requires an sm_103a/f device pass)
#if defined(__CUDA_ARCH_FEAT_SM103_ALL) || defined(__CUDA_ARCH_SPECIFIC__) || defined(__CUDA_ARCH_FAMILY_SPECIFIC__)
#define HAS_TCGEN05 1
#else
#define HAS_TCGEN05 0
#endif

// ---------------- device scratch ----------------
__device__ __nv_bfloat16 g_imgb[(size_t)B_IMG * D_DIM];
__device__ __nv_bfloat16 g_txtb[(size_t)N_TXT * D_DIM];
__device__ float g_rowsum[B_IMG];
__device__ float g_colsum[N_TXT];
__device__ float g_possum;            // RAW (unscaled) positive-logit sum
__device__ float g_logsum;
__device__ unsigned int g_count;

// ---------------- convert + init (fused) ----------------
__global__ void convert_kernel(const float* __restrict__ img,
                               const float* __restrict__ txt) {
    const int gid = blockIdx.x * blockDim.x + threadIdx.x;
    // zero accumulators (replay-safe)
    if (gid < B_IMG) g_rowsum[gid] = 0.0f;
    if (gid < N_TXT) g_colsum[gid] = 0.0f;
    if (gid == 0) { g_possum = 0.0f; g_logsum = 0.0f; g_count = 0u; }

    const int IMG4 = B_IMG * D_DIM / 4;
    const int TOT4 = IMG4 + N_TXT * D_DIM / 4;
    for (int i = gid; i < TOT4; i += gridDim.x * blockDim.x) {
        float4 v; __nv_bfloat16* dst;
        if (i < IMG4) { v = reinterpret_cast<const float4*>(img)[i]; dst = g_imgb + 4 * (size_t)i; }
        else { int j = i - IMG4; v = reinterpret_cast<const float4*>(txt)[j]; dst = g_txtb + 4 * (size_t)j; }
        reinterpret_cast<__nv_bfloat162*>(dst)[0] = __floats2bfloat162_rn(v.x, v.y);
        reinterpret_cast<__nv_bfloat162*>(dst)[1] = __floats2bfloat162_rn(v.z, v.w);
    }
}

// ================= PATH A: tcgen05 cg2 (2-CTA cluster, M=256) =================
// Cluster (2,1,1): cluster m-tile = 256 rows (128 per CTA), N tile = 512.
// Each CTA holds its own A (128 rows) and its B half: for dispatch-half nh,
// rows [nh*256 + rank*128, +128) of the 512-row B tile. B L2 traffic halves.
#define TC_BK 64                       // 128 bytes/row = SW128 atom
#define TC_NCHUNK (D_DIM / TC_BK)      // 8

#define SM_TMEMPTR 0u
#define SM_FULL0   8u
#define SM_FULL1   16u
#define SM_DONE0   24u
#define SM_DONE1   32u
#define SM_A0      1024u
#define SM_A1      17408u              // +16KB
#define SM_B0      33792u              // +16KB
#define SM_B1      66560u              // +32KB
#define SM_TOTAL   99840u              // +32KB + pad

// idesc cg2: f32 accum, bf16 A/B, N=256 per dispatch, M=256
#define MMA_IDESC_CG2 ((1u<<4)|(1u<<7)|(1u<<10)|((256u/8u)<<17)|((256u/16u)<<24))
#define SWZ(x) ((x) ^ (((x) >> 3) & 0x70))

__device__ __forceinline__ uint32_t smem_u32(const void* p) {
    return (uint32_t)__cvta_generic_to_shared(p);
}
__device__ __forceinline__ void cp16(uint32_t saddr, const void* g) {
    asm volatile("cp.async.cg.shared.global [%0], [%1], 16;\n" ::"r"(saddr), "l"(g));
}
__device__ __forceinline__ void mbar_init(uint32_t a, uint32_t cnt) {
    asm volatile("mbarrier.init.shared.b64 [%0], %1;" ::"r"(a), "r"(cnt) : "memory");
}
__device__ __forceinline__ void mbar_wait(uint32_t a, uint32_t parity) {
    uint32_t done;
    asm volatile(
        "{\n\t.reg .pred p;\n\t"
        "mbarrier.try_wait.parity.acquire.cta.shared::cta.b64 p, [%1], %2;\n\t"
        "selp.b32 %0, 1, 0, p;\n\t}"
        : "=r"(done) : "r"(a), "r"(parity) : "memory");
    if (!done) {
        asm volatile(
            "{\n\t.reg .pred P1;\n\t"
            "W_%=:\n\t"
            "mbarrier.try_wait.parity.acquire.cta.shared::cta.b64 P1, [%0], %1, 0x989680;\n\t"
            "@P1 bra.uni D_%=;\n\t"
            "bra.uni W_%=;\n\t"
            "D_%=:\n\t}"
            :: "r"(a), "r"(parity) : "memory");
    }
}
__device__ __forceinline__ void mbar_wait_cluster(uint32_t a, uint32_t parity) {
    asm volatile(
        "{\n\t.reg .pred P1;\n\t"
        "W_%=:\n\t"
        "mbarrier.try_wait.parity.acquire.cluster.shared::cta.b64 P1, [%0], %1, 0x989680;\n\t"
        "@P1 bra.uni D_%=;\n\t"
        "bra.uni W_%=;\n\t"
        "D_%=:\n\t}"
        :: "r"(a), "r"(parity) : "memory");
}
__device__ __forceinline__ void mbar_arrive_rank0(uint32_t local_addr) {
    asm volatile(
        "{\n\t.reg .b32 r;\n\t"
        "mapa.shared::cluster.u32 r, %0, 0;\n\t"
        "mbarrier.arrive.shared::cluster.b64 _, [r];\n\t}"
        :: "r"(local_addr) : "memory");
}

#if HAS_TCGEN05
__device__ __forceinline__ uint64_t make_desc_sw128(uint32_t addr) {
    const uint64_t base = (uint64_t(2) << 61) | (uint64_t(1) << 46) |
                          (uint64_t(64) << 32) | (uint64_t(1) << 16);
    return base | ((uint64_t)(addr >> 4) & 0x3FFF);
}
__device__ __forceinline__ void mma_f16_ss_cg2(uint32_t d, uint64_t ad, uint64_t bd,
                                               uint32_t idesc, uint32_t en) {
    asm volatile(
        "{\n\t.reg .pred p;\n\t"
        "setp.ne.u32 p, %4, 0;\n\t"
        "tcgen05.mma.cta_group::2.kind::f16 [%0], %1, %2, %3, "
        "{%5,%5,%5,%5,%5,%5,%5,%5}, p;\n\t}"
        :: "r"(d), "l"(ad), "l"(bd), "r"(idesc), "r"(en), "r"(0u) : "memory");
}
__device__ __forceinline__ void tc_load_chunk(uint32_t smem_base, int buf, int kc,
                                              int rowBase, int colBase, int rank,
                                              int tid) {
    uint32_t aoff = buf ? SM_A1 : SM_A0;
    uint32_t boff = buf ? SM_B1 : SM_B0;
    const __nv_bfloat16* srcA = g_imgb + (size_t)rowBase * D_DIM + kc * TC_BK;
#pragma unroll
    for (int i = 0; i < 4; i++) {          // A: 128 rows x 128B = 1024 x16B
        int idx = tid + i * 256;
        int row = idx >> 3, seg = idx & 7;
        cp16(smem_base + aoff + SWZ((uint32_t)(row * 128 + seg * 16)),
             srcA + (size_t)row * D_DIM + seg * 8);
    }
#pragma unroll
    for (int i = 0; i < 8; i++) {          // B: 256 local rows x 128B = 2048 x16B
        int idx = tid + i * 256;
        int lr = idx >> 3, seg = idx & 7;
        // local row lr -> global text row within tile
        int grow = colBase + ((lr >> 7) << 8) + rank * 128 + (lr & 127);
        cp16(smem_base + boff + SWZ((uint32_t)(lr * 128 + seg * 16)),
             g_txtb + (size_t)grow * D_DIM + kc * TC_BK + seg * 8);
    }
    asm volatile("cp.async.commit_group;\n" ::: "memory");
}
#endif  // HAS_TCGEN05

__global__ void __launch_bounds__(256, 1) __cluster_dims__(2, 1, 1)
gemm_tc_kernel() {
#if HAS_TCGEN05
    extern __shared__ char smem[];
    uint32_t smem_base = smem_u32(smem);
    const int tid = threadIdx.x;
    const int w = tid >> 5, lane = tid & 31;
    uint32_t rank;
    asm("mov.u32 %0, %%cluster_ctarank;" : "=r"(rank));
    const int rowBase = (blockIdx.x >> 1) * 256 + (int)rank * 128;
    const int colBase = blockIdx.y * 512;

    if (w == 0) {
        asm volatile("tcgen05.alloc.cta_group::2.sync.aligned.shared::cta.b32 [%0], %1;"
                     ::"r"(smem_base + SM_TMEMPTR), "r"(512u) : "memory");
        asm volatile("tcgen05.relinquish_alloc_permit.cta_group::2.sync.aligned;");
    }
    if (tid == 0) {
        mbar_init(smem_base + SM_FULL0, 2);   // one arrive per CTA
        mbar_init(smem_base + SM_FULL1, 2);
        mbar_init(smem_base + SM_DONE0, 1);   // multicast commit
        mbar_init(smem_base + SM_DONE1, 1);
    }
    __syncthreads();
    // cluster-wide: barriers + TMEM alloc visible before any cross-CTA traffic
    asm volatile("barrier.cluster.arrive.aligned;" ::: "memory");
    asm volatile("barrier.cluster.wait.aligned;" ::: "memory");

    uint32_t tmem_base;
    asm volatile("ld.shared.b32 %0, [%1];" : "=r"(tmem_base) : "r"(smem_base + SM_TMEMPTR));

    tc_load_chunk(smem_base, 0, 0, rowBase, colBase, (int)rank, tid);

#pragma unroll 1
    for (int c = 0; c < TC_NCHUNK; c++) {
        if (c + 1 < TC_NCHUNK) {
            if (c >= 1) {
                // buffer (c+1)&1 was consumed by MMA chunk c-1: wait its done
                uint32_t mb = ((c - 1) & 1) ? (smem_base + SM_DONE1) : (smem_base + SM_DONE0);
                mbar_wait(mb, ((c - 1) >> 1) & 1);
            }
            tc_load_chunk(smem_base, (c + 1) & 1, c + 1, rowBase, colBase, (int)rank, tid);
            asm volatile("cp.async.wait_group 1;\n" ::: "memory");
        } else {
            asm volatile("cp.async.wait_group 0;\n" ::: "memory");
        }
        __syncthreads();

        if (tid == 0) {
            asm volatile("fence.proxy.async.shared::cta;" ::: "memory");
            uint32_t fullb = (c & 1) ? SM_FULL1 : SM_FULL0;
            mbar_arrive_rank0(smem_base + fullb);   // both CTAs arrive on leader
            if (rank == 0) {
                mbar_wait_cluster(smem_base + fullb, (c >> 1) & 1);
                uint32_t abase = smem_base + ((c & 1) ? SM_A1 : SM_A0);
                uint32_t bbase = smem_base + ((c & 1) ? SM_B1 : SM_B0);
                uint64_t ad = make_desc_sw128(abase);
                uint64_t bd = make_desc_sw128(bbase);
#pragma unroll
                for (int nh = 0; nh < 2; nh++)
#pragma unroll
                    for (int k = 0; k < 4; k++)
                        mma_f16_ss_cg2(tmem_base + nh * 256,
                                       ad + k * 2,
                                       bd + nh * 1024 + k * 2,   // 128 rows x 128B / 16
                                       MMA_IDESC_CG2,
                                       (uint32_t)((c > 0) || (k > 0)));
                uint32_t db = (c & 1) ? SM_DONE1 : SM_DONE0;
                asm volatile(
                    "tcgen05.commit.cta_group::2.mbarrier::arrive::one"
                    ".shared::cluster.multicast::cluster.b64 [%0], %1;"
                    ::"r"(smem_base + db), "h"((uint16_t)0x3) : "memory");
            }
        }
    }

    // chunk 7's done: done1, 4th completion -> parity 1
    mbar_wait(smem_base + SM_DONE1, 1);
    asm volatile("tcgen05.fence::after_thread_sync;" ::: "memory");

    // ---- epilogue: 8 warps; warp w: rows (w&3)*32+lane, col-half w>>2 ----
    const int half = w >> 2, sp = w & 3;
    const int row = rowBase + sp * 32 + lane;
    float rowacc = 0.0f, pos = 0.0f;
    const int pstart = row * V_TXT - colBase - half * 256;

#pragma unroll 1
    for (int ch = 0; ch < 8; ch++) {
        uint32_t r[32];
        uint32_t taddr = tmem_base + half * 256 + ch * 32;
        asm volatile(
            "tcgen05.ld.sync.aligned.32x32b.x32.b32 "
            "{%0,%1,%2,%3,%4,%5,%6,%7,%8,%9,%10,%11,%12,%13,%14,%15,"
            "%16,%17,%18,%19,%20,%21,%22,%23,%24,%25,%26,%27,%28,%29,%30,%31}, [%32];"
            : "=r"(r[0]), "=r"(r[1]), "=r"(r[2]), "=r"(r[3]), "=r"(r[4]), "=r"(r[5]),
              "=r"(r[6]), "=r"(r[7]), "=r"(r[8]), "=r"(r[9]), "=r"(r[10]), "=r"(r[11]),
              "=r"(r[12]), "=r"(r[13]), "=r"(r[14]), "=r"(r[15]), "=r"(r[16]), "=r"(r[17]),
              "=r"(r[18]), "=r"(r[19]), "=r"(r[20]), "=r"(r[21]), "=r"(r[22]), "=r"(r[23]),
              "=r"(r[24]), "=r"(r[25]), "=r"(r[26]), "=r"(r[27]), "=r"(r[28]), "=r"(r[29]),
              "=r"(r[30]), "=r"(r[31])
            : "r"(taddr));
        asm volatile("tcgen05.wait::ld.sync.aligned;" ::: "memory");

        float v[32];
#pragma unroll
        for (int cc = 0; cc < 32; cc++) {
            float a = __uint_as_float(r[cc]);
            int lc = ch * 32 + cc;
            if (lc >= pstart && lc < pstart + V_TXT) pos += a;
            float e = __expf(fmaf(a, SCALE_F, -MSHIFT_F));
            v[cc] = e;
            rowacc += e;
        }
#pragma unroll
        for (int off = 16; off >= 1; off >>= 1) {
#pragma unroll
            for (int cc = 0; cc < 16; cc++) {
                if (cc < off) {
                    float sent = (lane & off) ? v[cc] : v[cc + off];
                    float rcv = __shfl_xor_sync(0xffffffffu, sent, off);
                    float keep = (lane & off) ? v[cc + off] : v[cc];
                    v[cc] = keep + rcv;
                }
            }
        }
        atomicAdd(&g_colsum[colBase + half * 256 + ch * 32 + lane], v[0]);
    }
    atomicAdd(&g_rowsum[row], rowacc);
    if (pos != 0.0f) atomicAdd(&g_possum, pos);

    __syncthreads();
    if (w == 0) {
        asm volatile("tcgen05.relinquish_alloc_permit.cta_group::2.sync.aligned;");
        asm volatile("tcgen05.dealloc.cta_group::2.sync.aligned.b32 %0, %1;"
                     ::"r"(tmem_base), "r"(512u));
    }
    asm volatile("barrier.cluster.arrive.aligned;" ::: "memory");
    asm volatile("barrier.cluster.wait.aligned;" ::: "memory");
#endif  // HAS_TCGEN05
}

// ================= PATH B: HMMA mma.sync fallback (plain sm_103) =============
__device__ __forceinline__ void mma16816(float* c, const uint32_t* a, const uint32_t* b) {
    asm volatile(
        "mma.sync.aligned.m16n8k16.row.col.f32.bf16.bf16.f32 "
        "{%0,%1,%2,%3}, {%4,%5,%6,%7}, {%8,%9}, {%0,%1,%2,%3};\n"
        : "+f"(c[0]), "+f"(c[1]), "+f"(c[2]), "+f"(c[3])
        : "r"(a[0]), "r"(a[1]), "r"(a[2]), "r"(a[3]), "r"(b[0]), "r"(b[1]));
}
__device__ __forceinline__ void cpa16(void* smem_dst, const void* gsrc) {
    uint32_t s = (uint32_t)__cvta_generic_to_shared(smem_dst);
    asm volatile("cp.async.ca.shared.global [%0], [%1], 16;\n" ::"r"(s), "l"(gsrc));
}
#define LDH 24
#define STAGE_H (128 * LDH)

__global__ void __launch_bounds__(256, 2) gemm_hmma_kernel() {
#if !HAS_TCGEN05
    __shared__ __nv_bfloat16 As[2 * STAGE_H];
    __shared__ __nv_bfloat16 Bs[2 * STAGE_H];

    const int tid = threadIdx.x;
    const int lane = tid & 31;
    const int warp = tid >> 5;
    const int g = lane >> 2;
    const int t = lane & 3;
    const int warpM = warp >> 2;
    const int warpN = warp & 3;
    const int rowBase = blockIdx.y * 128;
    const int colBase = blockIdx.x * 128;

    const int ldRow = tid >> 1;
    const int ldHalf = (tid & 1) * 8;
    const __nv_bfloat16* gA = g_imgb + (size_t)(rowBase + ldRow) * D_DIM + ldHalf;
    const __nv_bfloat16* gB = g_txtb + (size_t)(colBase + ldRow) * D_DIM + ldHalf;
    __nv_bfloat16* sA = &As[ldRow * LDH + ldHalf];
    __nv_bfloat16* sB = &Bs[ldRow * LDH + ldHalf];

    float acc[4][4][4];
#pragma unroll
    for (int mi = 0; mi < 4; mi++)
#pragma unroll
        for (int ni = 0; ni < 4; ni++)
#pragma unroll
            for (int r = 0; r < 4; r++) acc[mi][ni][r] = 0.0f;

    cpa16(sA, gA);
    cpa16(sB, gB);
    asm volatile("cp.async.commit_group;\n" ::: "memory");

    const int NSTEP = D_DIM / 16;
#pragma unroll 1
    for (int kc = 0; kc < NSTEP; kc++) {
        if (kc + 1 < NSTEP) {
            int st = (kc + 1) & 1;
            int k0 = (kc + 1) * 16;
            cpa16(sA + st * STAGE_H, gA + k0);
            cpa16(sB + st * STAGE_H, gB + k0);
            asm volatile("cp.async.commit_group;\n" ::: "memory");
            asm volatile("cp.async.wait_group 1;\n" ::: "memory");
        } else {
            asm volatile("cp.async.wait_group 0;\n" ::: "memory");
        }
        __syncthreads();

        const int buf = kc & 1;
        const uint32_t* A32 = reinterpret_cast<const uint32_t*>(As + buf * STAGE_H);
        const uint32_t* B32 = reinterpret_cast<const uint32_t*>(Bs + buf * STAGE_H);

        uint32_t a[4][4], b[4][2];
#pragma unroll
        for (int mi = 0; mi < 4; mi++) {
            int r0 = warpM * 64 + mi * 16 + g;
            a[mi][0] = A32[r0 * (LDH / 2) + t];
            a[mi][1] = A32[(r0 + 8) * (LDH / 2) + t];
            a[mi][2] = A32[r0 * (LDH / 2) + t + 4];
            a[mi][3] = A32[(r0 + 8) * (LDH / 2) + t + 4];
        }
#pragma unroll
        for (int ni = 0; ni < 4; ni++) {
            int c0 = warpN * 32 + ni * 8 + g;
            b[ni][0] = B32[c0 * (LDH / 2) + t];
            b[ni][1] = B32[c0 * (LDH / 2) + t + 4];
        }
#pragma unroll
        for (int mi = 0; mi < 4; mi++)
#pragma unroll
            for (int ni = 0; ni < 4; ni++) mma16816(acc[mi][ni], a[mi], b[ni]);

        __syncthreads();
    }

    float rp[4][2], cp[4][2];
#pragma unroll
    for (int i = 0; i < 4; i++) { rp[i][0] = rp[i][1] = cp[i][0] = cp[i][1] = 0.0f; }
    float pos = 0.0f;

#pragma unroll
    for (int mi = 0; mi < 4; mi++) {
        const int r0 = rowBase + warpM * 64 + mi * 16 + g;
        const int r1 = r0 + 8;
#pragma unroll
        for (int ni = 0; ni < 4; ni++) {
            const int c0 = colBase + warpN * 32 + ni * 8 + 2 * t;
            const int c1 = c0 + 1;
            float e00 = __expf(fmaf(acc[mi][ni][0], SCALE_F, -MSHIFT_F));
            float e01 = __expf(fmaf(acc[mi][ni][1], SCALE_F, -MSHIFT_F));
            float e10 = __expf(fmaf(acc[mi][ni][2], SCALE_F, -MSHIFT_F));
            float e11 = __expf(fmaf(acc[mi][ni][3], SCALE_F, -MSHIFT_F));
            rp[mi][0] += e00 + e01;
            rp[mi][1] += e10 + e11;
            cp[ni][0] += e00 + e10;
            cp[ni][1] += e01 + e11;
            int p0 = r0 * V_TXT;
            int p1 = r1 * V_TXT;
            if (c0 >= p0 && c0 < p0 + V_TXT) pos += acc[mi][ni][0];  // RAW
            if (c1 >= p0 && c1 < p0 + V_TXT) pos += acc[mi][ni][1];
            if (c0 >= p1 && c0 < p1 + V_TXT) pos += acc[mi][ni][2];
            if (c1 >= p1 && c1 < p1 + V_TXT) pos += acc[mi][ni][3];
        }
    }

#pragma unroll
    for (int mi = 0; mi < 4; mi++)
#pragma unroll
        for (int rr = 0; rr < 2; rr++) {
            float v = rp[mi][rr];
            v += __shfl_xor_sync(0xffffffffu, v, 1);
            v += __shfl_xor_sync(0xffffffffu, v, 2);
            if (t == 0)
                atomicAdd(&g_rowsum[rowBase + warpM * 64 + mi * 16 + g + rr * 8], v);
        }
#pragma unroll
    for (int ni = 0; ni < 4; ni++)
#pragma unroll
        for (int cc = 0; cc < 2; cc++) {
            float v = cp[ni][cc];
            v += __shfl_xor_sync(0xffffffffu, v, 4);
            v += __shfl_xor_sync(0xffffffffu, v, 8);
            v += __shfl_xor_sync(0xffffffffu, v, 16);
            if (g == 0)
                atomicAdd(&g_colsum[colBase + warpN * 32 + ni * 8 + 2 * t + cc], v);
        }
    if (pos != 0.0f) atomicAdd(&g_possum, pos);
#endif  // !HAS_TCGEN05
}

// ---------------- parallel log reduction + fused writer ----------------
#define RED_BLOCKS 64
__global__ void reduce_kernel(float* out, int out_size) {
    float s = 0.0f;
    for (int i = blockIdx.x * blockDim.x + threadIdx.x; i < B_IMG;
         i += gridDim.x * blockDim.x)
        s += logf(g_rowsum[i]) * (1.0f / B_IMG);
    for (int j = blockIdx.x * blockDim.x + threadIdx.x; j < N_TXT;
         j += gridDim.x * blockDim.x)
        s += logf(g_colsum[j]) * (1.0f / N_TXT);
#pragma unroll
    for (int off = 16; off >= 1; off >>= 1) s += __shfl_xor_sync(0xffffffffu, s, off);
    __shared__ float sh[8];
    int w = threadIdx.x >> 5, lane = threadIdx.x & 31;
    if (lane == 0) sh[w] = s;
    __syncthreads();
    if (threadIdx.x == 0) {
        float b = 0.0f;
        for (int k = 0; k < 8; k++) b += sh[k];
        atomicAdd(&g_logsum, b);
        __threadfence();
        unsigned int done = atomicAdd(&g_count, 1u);
        if (done == RED_BLOCKS - 1) {
            float loss = 0.5f * (g_logsum + 2.0f * MSHIFT_F)
                         - SCALE_F * g_possum / (float)N_TXT;
            for (int k = 0; k < out_size; k++) out[k] = loss;
        }
    }
}

// ---------------- launch ----------------
extern "C" void kernel_launch(void* const* d_in, const int* in_sizes, int n_in,
                              void* d_out, int out_size) {
    const float* img = (const float*)d_in[0];
    const float* txt = (const float*)d_in[1];
    (void)in_sizes; (void)n_in;

    // Per-binary (deterministic) path detection: the inactive kernel body is
    // compiled empty (<= ~16 regs); the live tcgen05 kernel needs far more.
    static int use_tc = -1;
    if (use_tc < 0) {
        cudaFuncAttributes a{};
        cudaFuncGetAttributes(&a, gemm_tc_kernel);
        use_tc = (a.numRegs > 40) ? 1 : 0;
        if (use_tc)
            cudaFuncSetAttribute(gemm_tc_kernel,
                                 cudaFuncAttributeMaxDynamicSharedMemorySize, SM_TOTAL);
    }

    convert_kernel<<<2048, 256>>>(img, txt);
    if (use_tc) {
        dim3 grid_tc(2 * (B_IMG / 256), N_TXT / 512);   // (32, 40), clusters of 2 on x
        gemm_tc_kernel<<<grid_tc, 256, SM_TOTAL>>>();
    } else {
        dim3 grid_hm(N_TXT / 128, B_IMG / 128);         // (160, 32)
        gemm_hmma_kernel<<<grid_hm, 256>>>();
    }
    reduce_kernel<<<RED_BLOCKS, 256>>>((float*)d_out, out_size);
}